// round 15
// baseline (speedup 1.0000x reference)
#include <cuda_runtime.h>
#include <cuda_fp16.h>

// Problem constants (fixed by the dataset)
#define NN 100000
#define EE 1600000
#define HCF 128      // H*C
#define HH 4
#define GG 16
#define NEG_SLOPE 0.2f
#define MT 16        // nodes per gemm block
#define NB_SCAN ((NN + 1023) / 1024)   // 98 scan blocks

// ---------------- static device scratch (no allocations allowed) -------------
__device__ __align__(16) __half g_h16[(size_t)NN * HCF];       // 25.6 MB (fp16 h)
__device__ __align__(16) float  g_asrc[NN * HH];
__device__ __align__(16) float  g_adst[NN * HH];
__device__ int   g_deg[NN];
__device__ int   g_ptr[NN];
__device__ int   g_cursor[NN];
__device__ int   g_bsum[128];
__device__ __align__(16) int4 g_rec[EE];                       // 25.6 MB packed CSR
__device__ float g_gsum[GG * HCF];
__device__ float g_gss[GG * HCF];
__device__ int   g_gcnt[GG];
__device__ float g_ce[HH];
__device__ __align__(16) float g_A[GG * HCF];
__device__ __align__(16) float g_B[GG * HCF];

// ---------------- K0: init + per-head edge constant --------------------------
__global__ void k_init(const float* __restrict__ W_edge,
                       const float* __restrict__ att_edge) {
    int idx = blockIdx.x * blockDim.x + threadIdx.x;
    if (idx < NN)      g_deg[idx] = 0;
    if (idx < GG * HCF) { g_gsum[idx] = 0.0f; g_gss[idx] = 0.0f; }
    if (idx < GG)      g_gcnt[idx] = 0;
    if (blockIdx.x == 0 && threadIdx.x < HCF) {
        int j = threadIdx.x;
        float v = W_edge[j] * att_edge[j];
        #pragma unroll
        for (int o = 16; o > 0; o >>= 1)
            v += __shfl_down_sync(0xffffffffu, v, o);
        if ((j & 31) == 0) g_ce[j >> 5] = v;
    }
}

__device__ __forceinline__ float wred(float v) {
    #pragma unroll
    for (int o = 16; o > 0; o >>= 1)
        v += __shfl_down_sync(0xffffffffu, v, o);
    return v;
}

// ---------------- K1: h = x @ W (packed f32x2), plus a_src/a_dst -------------
// 128 threads (thread j = output feature), MT=16 nodes per block.
// Inner loop reads the node tile via LDS.128 (one ulonglong2 = two f32x2
// operand pairs), cutting LSU ops per k from 9 (8x LDS.64 + LDG) to 5.
__global__ void k_gemm(const float* __restrict__ x, const float* __restrict__ W,
                       const float* __restrict__ att_src,
                       const float* __restrict__ att_dst) {
    __shared__ __align__(16) float xs[HCF][MT + 4];   // row stride 80 B (16B-aligned)
    const int j  = threadIdx.x;
    const int n0 = blockIdx.x * MT;

    #pragma unroll
    for (int m = 0; m < MT; m++)
        xs[j][m] = x[(size_t)(n0 + m) * HCF + j];
    __syncthreads();

    unsigned long long acc[MT / 2];
    #pragma unroll
    for (int p = 0; p < MT / 2; p++) acc[p] = 0ull;

    #pragma unroll 4
    for (int k = 0; k < HCF; k++) {
        float w = W[k * HCF + j];
        unsigned long long w2;
        asm("mov.b64 %0, {%1, %1};" : "=l"(w2) : "f"(w));
        #pragma unroll
        for (int q = 0; q < MT / 4; q++) {
            ulonglong2 a = *reinterpret_cast<const ulonglong2*>(&xs[k][4 * q]);
            asm("fma.rn.f32x2 %0, %1, %2, %3;"
                : "=l"(acc[2 * q]) : "l"(a.x), "l"(w2), "l"(acc[2 * q]));
            asm("fma.rn.f32x2 %0, %1, %2, %3;"
                : "=l"(acc[2 * q + 1]) : "l"(a.y), "l"(w2), "l"(acc[2 * q + 1]));
        }
    }

    const float as = att_src[j];
    const float ad = att_dst[j];
    const int head = j >> 5, lane = j & 31;
    #pragma unroll
    for (int p = 0; p < MT / 2; p++) {
        float2 v = *reinterpret_cast<float2*>(&acc[p]);
        g_h16[(size_t)(n0 + 2 * p) * HCF + j]     = __float2half_rn(v.x);
        g_h16[(size_t)(n0 + 2 * p + 1) * HCF + j] = __float2half_rn(v.y);
        float s0 = wred(v.x * as);
        float d0 = wred(v.x * ad);
        float s1 = wred(v.y * as);
        float d1 = wred(v.y * ad);
        if (lane == 0) {
            g_asrc[(n0 + 2 * p) * HH + head]     = s0;
            g_adst[(n0 + 2 * p) * HH + head]     = d0;
            g_asrc[(n0 + 2 * p + 1) * HH + head] = s1;
            g_adst[(n0 + 2 * p + 1) * HH + head] = d1;
        }
    }
}

// ---------------- K2: dst-degree histogram -----------------------------------
__global__ void k_deg(const int* __restrict__ ei) {
    int e = blockIdx.x * blockDim.x + threadIdx.x;
    if (e < EE) atomicAdd(&g_deg[__ldg(&ei[EE + e])], 1);
}

// ---------------- K3a: block-wise inclusive scan of degrees ------------------
__global__ void k_scan_a() {
    __shared__ int sh[1024];
    const int t = threadIdx.x;
    const int i = blockIdx.x * 1024 + t;
    const int v = (i < NN) ? g_deg[i] : 0;
    sh[t] = v;
    __syncthreads();
    #pragma unroll
    for (int o = 1; o < 1024; o <<= 1) {
        int u = (t >= o) ? sh[t - o] : 0;
        __syncthreads();
        sh[t] += u;
        __syncthreads();
    }
    if (i < NN) g_ptr[i] = sh[t] - v;
    if (t == 1023) g_bsum[blockIdx.x] = sh[1023];
}

// ---------------- K3b: scan the block totals ---------------------------------
__global__ void k_scan_b() {
    __shared__ int sh[128];
    const int t = threadIdx.x;
    const int v = (t < NB_SCAN) ? g_bsum[t] : 0;
    sh[t] = v;
    __syncthreads();
    #pragma unroll
    for (int o = 1; o < 128; o <<= 1) {
        int u = (t >= o) ? sh[t - o] : 0;
        __syncthreads();
        sh[t] += u;
        __syncthreads();
    }
    if (t < NB_SCAN) g_bsum[t] = sh[t] - v;
}

// ---------------- K3c: add block offsets, init cursor ------------------------
__global__ void k_scan_c() {
    int i = blockIdx.x * blockDim.x + threadIdx.x;
    if (i < NN) {
        int p = g_ptr[i] + g_bsum[i >> 10];
        g_ptr[i] = p;
        g_cursor[i] = p;
    }
}

// ---------------- K4: alpha -> leaky -> exp -> packed CSR record -------------
__global__ void k_edge(const int* __restrict__ ei, const float* __restrict__ ea) {
    int e = blockIdx.x * blockDim.x + threadIdx.x;
    if (e >= EE) return;
    const int src = ei[e];
    const int dst = ei[EE + e];
    const float4 as = *reinterpret_cast<const float4*>(&g_asrc[src * HH]);
    const float4 ad = *reinterpret_cast<const float4*>(&g_adst[dst * HH]);
    const float w = ea[e];
    float al0 = as.x + ad.x + w * g_ce[0];
    float al1 = as.y + ad.y + w * g_ce[1];
    float al2 = as.z + ad.z + w * g_ce[2];
    float al3 = as.w + ad.w + w * g_ce[3];
    al0 = (al0 >= 0.0f) ? al0 : NEG_SLOPE * al0;
    al1 = (al1 >= 0.0f) ? al1 : NEG_SLOPE * al1;
    al2 = (al2 >= 0.0f) ? al2 : NEG_SLOPE * al2;
    al3 = (al3 >= 0.0f) ? al3 : NEG_SLOPE * al3;
    __half2 e01 = __floats2half2_rn(__expf(al0), __expf(al1));
    __half2 e23 = __floats2half2_rn(__expf(al2), __expf(al3));
    int4 rec;
    rec.x = src;
    rec.y = *reinterpret_cast<int*>(&e01);
    rec.z = *reinterpret_cast<int*>(&e23);
    rec.w = 0;
    int pos = atomicAdd(&g_cursor[dst], 1);
    g_rec[pos] = rec;
}

// ---------------- K5: gather-aggregate (independent warp per dst node) -------
__device__ __forceinline__ float rec_w(const int4& r, int h) {
    int raw = (h < 2) ? r.y : r.z;
    __half2 pair = *reinterpret_cast<__half2*>(&raw);
    float2 f = __half22float2(pair);
    return (h & 1) ? f.y : f.x;
}

__global__ void k_agg(const float* __restrict__ bias, float* __restrict__ out) {
    const int n = (blockIdx.x * blockDim.x + threadIdx.x) >> 5;
    if (n >= NN) return;
    const int lane = threadIdx.x & 31;
    const int start = g_ptr[n];
    const int deg = g_deg[n];
    const int h = lane >> 3;

    float4 acc = make_float4(0.f, 0.f, 0.f, 0.f);
    float dsum = 0.0f;
    int i = start;
    const int end = start + deg;
    for (; i + 4 <= end; i += 4) {
        const int4 r0 = __ldg(&g_rec[i]);
        const int4 r1 = __ldg(&g_rec[i + 1]);
        const int4 r2 = __ldg(&g_rec[i + 2]);
        const int4 r3 = __ldg(&g_rec[i + 3]);
        const float w0 = rec_w(r0, h), w1 = rec_w(r1, h);
        const float w2 = rec_w(r2, h), w3 = rec_w(r3, h);
        const unsigned long long hb0 = *reinterpret_cast<const unsigned long long*>(
            &g_h16[(size_t)r0.x * HCF + lane * 4]);
        const unsigned long long hb1 = *reinterpret_cast<const unsigned long long*>(
            &g_h16[(size_t)r1.x * HCF + lane * 4]);
        const unsigned long long hb2 = *reinterpret_cast<const unsigned long long*>(
            &g_h16[(size_t)r2.x * HCF + lane * 4]);
        const unsigned long long hb3 = *reinterpret_cast<const unsigned long long*>(
            &g_h16[(size_t)r3.x * HCF + lane * 4]);
        const __half2* p0 = reinterpret_cast<const __half2*>(&hb0);
        const __half2* p1 = reinterpret_cast<const __half2*>(&hb1);
        const __half2* p2 = reinterpret_cast<const __half2*>(&hb2);
        const __half2* p3 = reinterpret_cast<const __half2*>(&hb3);
        float2 a0 = __half22float2(p0[0]), b0 = __half22float2(p0[1]);
        float2 a1 = __half22float2(p1[0]), b1 = __half22float2(p1[1]);
        float2 a2 = __half22float2(p2[0]), b2 = __half22float2(p2[1]);
        float2 a3 = __half22float2(p3[0]), b3 = __half22float2(p3[1]);
        dsum += (w0 + w1) + (w2 + w3);
        acc.x += w0 * a0.x + w1 * a1.x + w2 * a2.x + w3 * a3.x;
        acc.y += w0 * a0.y + w1 * a1.y + w2 * a2.y + w3 * a3.y;
        acc.z += w0 * b0.x + w1 * b1.x + w2 * b2.x + w3 * b3.x;
        acc.w += w0 * b0.y + w1 * b1.y + w2 * b2.y + w3 * b3.y;
    }
    for (; i < end; i++) {
        const int4 r0 = __ldg(&g_rec[i]);
        const float w0 = rec_w(r0, h);
        const unsigned long long hb0 = *reinterpret_cast<const unsigned long long*>(
            &g_h16[(size_t)r0.x * HCF + lane * 4]);
        const __half2* p0 = reinterpret_cast<const __half2*>(&hb0);
        float2 a0 = __half22float2(p0[0]), b0 = __half22float2(p0[1]);
        dsum += w0;
        acc.x += w0 * a0.x; acc.y += w0 * a0.y;
        acc.z += w0 * b0.x; acc.w += w0 * b0.y;
    }
    const float inv = 1.0f / (dsum + 1e-16f);
    const float4 b4 = *reinterpret_cast<const float4*>(&bias[lane * 4]);
    acc.x = acc.x * inv + b4.x; acc.y = acc.y * inv + b4.y;
    acc.z = acc.z * inv + b4.z; acc.w = acc.w * inv + b4.w;
    *reinterpret_cast<float4*>(&out[(size_t)n * HCF + lane * 4]) = acc;
}

// ---------------- K6: group sum / sumsq / counts (sorted, flush-on-change) ---
__global__ void k_stats(const int* __restrict__ batch,
                        const float* __restrict__ out) {
    __shared__ int sb[64];
    const int b0 = blockIdx.x * 64;
    if (threadIdx.x < 64)
        sb[threadIdx.x] = (b0 + threadIdx.x < NN) ? batch[b0 + threadIdx.x] : -1;
    __syncthreads();
    const int j = threadIdx.x;   // 0..127
    float s = 0.f, ss = 0.f;
    int cnt = 0;
    int cur = sb[0];
    for (int i = 0; i < 64; i++) {
        int g = sb[i];
        if (g < 0) break;
        float v = out[(size_t)(b0 + i) * HCF + j];
        if (g != cur) {
            atomicAdd(&g_gsum[cur * HCF + j], s);
            atomicAdd(&g_gss[cur * HCF + j], ss);
            if (j == 0) atomicAdd(&g_gcnt[cur], cnt);
            s = 0.f; ss = 0.f; cnt = 0; cur = g;
        }
        s += v; ss += v * v; cnt++;
    }
    if (cur >= 0) {
        atomicAdd(&g_gsum[cur * HCF + j], s);
        atomicAdd(&g_gss[cur * HCF + j], ss);
        if (j == 0) atomicAdd(&g_gcnt[cur], cnt);
    }
}

// ---------------- K7: per (group, feature) affine params ---------------------
__global__ void k_params(const float* __restrict__ gnw,
                         const float* __restrict__ gnb,
                         const float* __restrict__ gms) {
    int idx = blockIdx.x * blockDim.x + threadIdx.x;
    if (idx >= GG * HCF) return;
    const int j = idx & (HCF - 1);
    int cnt = g_gcnt[idx >> 7];
    float fc = (float)(cnt > 0 ? cnt : 1);
    float m = g_gsum[idx] / fc;
    float sj = gms[j];
    float var = g_gss[idx] / fc - 2.0f * sj * m * m + sj * sj * m * m;
    float inv = rsqrtf(fmaxf(var, 0.0f) + 1e-5f);
    float A = gnw[j] * inv;
    g_A[idx] = A;
    g_B[idx] = gnb[j] - A * sj * m;
}

// ---------------- K8: normalize (out = out*A[g,j] + B[g,j]) ------------------
__global__ void k_norm(const int* __restrict__ batch, float* __restrict__ out) {
    int idx = blockIdx.x * blockDim.x + threadIdx.x;
    if (idx >= NN * (HCF / 4)) return;
    const int n = idx >> 5;
    const int off = (idx & 31) * 4;
    const int g = batch[n];
    float4 v = reinterpret_cast<float4*>(out)[idx];
    const float4 A = *reinterpret_cast<const float4*>(&g_A[g * HCF + off]);
    const float4 B = *reinterpret_cast<const float4*>(&g_B[g * HCF + off]);
    v.x = v.x * A.x + B.x; v.y = v.y * A.y + B.y;
    v.z = v.z * A.z + B.z; v.w = v.w * A.w + B.w;
    reinterpret_cast<float4*>(out)[idx] = v;
}

// ---------------- launch -----------------------------------------------------
extern "C" void kernel_launch(void* const* d_in, const int* in_sizes, int n_in,
                              void* d_out, int out_size) {
    const float *x = 0, *ea = 0, *W = 0;
    const int *ei = 0, *batch = 0;
    const float* small[8] = {0, 0, 0, 0, 0, 0, 0, 0};
    int nsmall = 0;
    for (int i = 0; i < n_in; i++) {
        int sz = in_sizes[i];
        if      (sz == NN * HCF)   x     = (const float*)d_in[i];
        else if (sz == 2 * EE)     ei    = (const int*)d_in[i];
        else if (sz == EE)         ea    = (const float*)d_in[i];
        else if (sz == HCF * HCF)  W     = (const float*)d_in[i];
        else if (sz == NN)         batch = (const int*)d_in[i];
        else if (sz == HCF && nsmall < 8) small[nsmall++] = (const float*)d_in[i];
    }
    const float* att_src  = small[0];
    const float* att_dst  = small[1];
    const float* W_edge   = small[2];
    const float* att_edge = small[3];
    const float* bias     = small[4];
    const float* gnw      = small[5];
    const float* gnb      = small[6];
    const float* gms      = small[7];
    float* out = (float*)d_out;

    // Lazy-created side stream + events (host objects, no device memory; made
    // on the correctness call, i.e. outside graph capture).
    static cudaStream_t s2 = 0;
    static cudaEvent_t evA = 0, evB = 0;
    if (!s2) {
        cudaStreamCreateWithFlags(&s2, cudaStreamNonBlocking);
        cudaEventCreateWithFlags(&evA, cudaEventDisableTiming);
        cudaEventCreateWithFlags(&evB, cudaEventDisableTiming);
    }

    k_init  <<<(NN + 255) / 256, 256>>>(W_edge, att_edge);
    cudaEventRecord(evA, 0);
    cudaStreamWaitEvent(s2, evA, 0);
    // Submission order keeps k_gemm as the 4th launch (ncu's capture index)
    // while execution order/dependencies are unchanged.
    k_deg   <<<(EE + 255) / 256, 256, 0, s2>>>(ei);
    k_scan_a<<<NB_SCAN, 1024, 0, s2>>>();
    k_gemm  <<<NN / MT, 128>>>(x, W, att_src, att_dst);
    k_scan_b<<<1, 128, 0, s2>>>();
    k_scan_c<<<(NN + 255) / 256, 256, 0, s2>>>();
    cudaEventRecord(evB, s2);

    // Join: k_edge needs both the GEMM outputs and the scan results.
    cudaStreamWaitEvent(0, evB, 0);
    k_edge  <<<(EE + 255) / 256, 256>>>(ei, ea);
    k_agg   <<<NN / 8, 256>>>(bias, out);
    k_stats <<<(NN + 63) / 64, 128>>>(batch, out);
    k_params<<<(GG * HCF + 255) / 256, 256>>>(gnw, gnb, gms);
    k_norm  <<<(NN * (HCF / 4) + 255) / 256, 256>>>(batch, out);
}

// round 16
// speedup vs baseline: 1.0200x; 1.0200x over previous
#include <cuda_runtime.h>
#include <cuda_fp16.h>

// Problem constants (fixed by the dataset)
#define NN 100000
#define EE 1600000
#define HCF 128      // H*C
#define HH 4
#define GG 16
#define NEG_SLOPE 0.2f
#define MT 16        // nodes per gemm block
#define NB_SCAN ((NN + 1023) / 1024)   // 98 scan blocks

// ---------------- static device scratch (no allocations allowed) -------------
__device__ __align__(16) __half g_h16[(size_t)NN * HCF];       // 25.6 MB (fp16 h)
__device__ __align__(16) float  g_asrc[NN * HH];
__device__ __align__(16) float  g_adst[NN * HH];
__device__ int   g_deg[NN];
__device__ int   g_ptr[NN];
__device__ int   g_cursor[NN];
__device__ int   g_bsum[128];
__device__ __align__(16) int4 g_rec[EE];                       // 25.6 MB packed CSR
__device__ float g_gsum[GG * HCF];
__device__ float g_gss[GG * HCF];
__device__ int   g_gcnt[GG];
__device__ float g_ce[HH];
__device__ __align__(16) float g_A[GG * HCF];
__device__ __align__(16) float g_B[GG * HCF];

// ---------------- K0: init + per-head edge constant --------------------------
__global__ void k_init(const float* __restrict__ W_edge,
                       const float* __restrict__ att_edge) {
    int idx = blockIdx.x * blockDim.x + threadIdx.x;
    if (idx < NN)      g_deg[idx] = 0;
    if (idx < GG * HCF) { g_gsum[idx] = 0.0f; g_gss[idx] = 0.0f; }
    if (idx < GG)      g_gcnt[idx] = 0;
    if (blockIdx.x == 0 && threadIdx.x < HCF) {
        int j = threadIdx.x;
        float v = W_edge[j] * att_edge[j];
        #pragma unroll
        for (int o = 16; o > 0; o >>= 1)
            v += __shfl_down_sync(0xffffffffu, v, o);
        if ((j & 31) == 0) g_ce[j >> 5] = v;
    }
}

// ---------------- K1: h = x @ W (packed f32x2), plus a_src/a_dst -------------
// 128 threads. Warp w handles nodes [n0+4w, n0+4w+4) x ALL 128 columns;
// thread (lane) owns 4 consecutive columns c0=lane*4. Per k the warp issues
// ONE coalesced LDG.128 of the W row and ONE broadcast LDS.128 of 4 node
// values: 6 LSU units per 8 FFMA2 vs 9 previously.
__global__ void k_gemm(const float* __restrict__ x, const float* __restrict__ W,
                       const float* __restrict__ att_src,
                       const float* __restrict__ att_dst) {
    __shared__ __align__(16) float xs[HCF][MT + 4];   // row stride 80 B (16B-aligned)
    const int tid = threadIdx.x;
    const int lane = tid & 31;
    const int c0 = lane * 4;            // this thread's 4 columns
    const int m0 = (tid >> 5) * 4;      // this warp's 4 nodes
    const int n0 = blockIdx.x * MT;

    #pragma unroll
    for (int m = 0; m < MT; m++)
        xs[tid][m] = x[(size_t)(n0 + m) * HCF + tid];
    __syncthreads();

    unsigned long long acc[4][2];
    #pragma unroll
    for (int m = 0; m < 4; m++) { acc[m][0] = 0ull; acc[m][1] = 0ull; }

    #pragma unroll 4
    for (int k = 0; k < HCF; k++) {
        const float4 wv = *reinterpret_cast<const float4*>(&W[k * HCF + c0]);
        const float4 xv = *reinterpret_cast<const float4*>(&xs[k][m0]);
        unsigned long long wlo, whi;
        asm("mov.b64 %0, {%1, %2};" : "=l"(wlo) : "f"(wv.x), "f"(wv.y));
        asm("mov.b64 %0, {%1, %2};" : "=l"(whi) : "f"(wv.z), "f"(wv.w));
        const float xm[4] = {xv.x, xv.y, xv.z, xv.w};
        #pragma unroll
        for (int m = 0; m < 4; m++) {
            unsigned long long a2;
            asm("mov.b64 %0, {%1, %1};" : "=l"(a2) : "f"(xm[m]));
            asm("fma.rn.f32x2 %0, %1, %2, %3;"
                : "=l"(acc[m][0]) : "l"(a2), "l"(wlo), "l"(acc[m][0]));
            asm("fma.rn.f32x2 %0, %1, %2, %3;"
                : "=l"(acc[m][1]) : "l"(a2), "l"(whi), "l"(acc[m][1]));
        }
    }

    const float4 as4 = *reinterpret_cast<const float4*>(&att_src[c0]);
    const float4 ad4 = *reinterpret_cast<const float4*>(&att_dst[c0]);
    const int head = lane >> 3;         // c0/32
    #pragma unroll
    for (int m = 0; m < 4; m++) {
        const int n = n0 + m0 + m;
        const float2 v0 = *reinterpret_cast<float2*>(&acc[m][0]);
        const float2 v1 = *reinterpret_cast<float2*>(&acc[m][1]);
        // fp16 store of 4 columns (8 B, coalesced across lanes)
        __half2 hl = __floats2half2_rn(v0.x, v0.y);
        __half2 hh = __floats2half2_rn(v1.x, v1.y);
        uint2 hb = make_uint2(*reinterpret_cast<unsigned*>(&hl),
                              *reinterpret_cast<unsigned*>(&hh));
        *reinterpret_cast<uint2*>(&g_h16[(size_t)n * HCF + c0]) = hb;
        // per-head dot: columns of one head live in 8 adjacent lanes
        float s = v0.x * as4.x + v0.y * as4.y + v1.x * as4.z + v1.y * as4.w;
        float d = v0.x * ad4.x + v0.y * ad4.y + v1.x * ad4.z + v1.y * ad4.w;
        #pragma unroll
        for (int o = 4; o > 0; o >>= 1) {
            s += __shfl_down_sync(0xffffffffu, s, o, 8);
            d += __shfl_down_sync(0xffffffffu, d, o, 8);
        }
        if ((lane & 7) == 0) {
            g_asrc[n * HH + head] = s;
            g_adst[n * HH + head] = d;
        }
    }
}

// ---------------- K2: dst-degree histogram -----------------------------------
__global__ void k_deg(const int* __restrict__ ei) {
    int e = blockIdx.x * blockDim.x + threadIdx.x;
    if (e < EE) atomicAdd(&g_deg[__ldg(&ei[EE + e])], 1);
}

// ---------------- K3a: block-wise inclusive scan of degrees ------------------
__global__ void k_scan_a() {
    __shared__ int sh[1024];
    const int t = threadIdx.x;
    const int i = blockIdx.x * 1024 + t;
    const int v = (i < NN) ? g_deg[i] : 0;
    sh[t] = v;
    __syncthreads();
    #pragma unroll
    for (int o = 1; o < 1024; o <<= 1) {
        int u = (t >= o) ? sh[t - o] : 0;
        __syncthreads();
        sh[t] += u;
        __syncthreads();
    }
    if (i < NN) g_ptr[i] = sh[t] - v;
    if (t == 1023) g_bsum[blockIdx.x] = sh[1023];
}

// ---------------- K3b: scan the block totals ---------------------------------
__global__ void k_scan_b() {
    __shared__ int sh[128];
    const int t = threadIdx.x;
    const int v = (t < NB_SCAN) ? g_bsum[t] : 0;
    sh[t] = v;
    __syncthreads();
    #pragma unroll
    for (int o = 1; o < 128; o <<= 1) {
        int u = (t >= o) ? sh[t - o] : 0;
        __syncthreads();
        sh[t] += u;
        __syncthreads();
    }
    if (t < NB_SCAN) g_bsum[t] = sh[t] - v;
}

// ---------------- K3c: add block offsets, init cursor ------------------------
__global__ void k_scan_c() {
    int i = blockIdx.x * blockDim.x + threadIdx.x;
    if (i < NN) {
        int p = g_ptr[i] + g_bsum[i >> 10];
        g_ptr[i] = p;
        g_cursor[i] = p;
    }
}

// ---------------- K4: alpha -> leaky -> exp -> packed CSR record -------------
__global__ void k_edge(const int* __restrict__ ei, const float* __restrict__ ea) {
    int e = blockIdx.x * blockDim.x + threadIdx.x;
    if (e >= EE) return;
    const int src = ei[e];
    const int dst = ei[EE + e];
    const float4 as = *reinterpret_cast<const float4*>(&g_asrc[src * HH]);
    const float4 ad = *reinterpret_cast<const float4*>(&g_adst[dst * HH]);
    const float w = ea[e];
    float al0 = as.x + ad.x + w * g_ce[0];
    float al1 = as.y + ad.y + w * g_ce[1];
    float al2 = as.z + ad.z + w * g_ce[2];
    float al3 = as.w + ad.w + w * g_ce[3];
    al0 = (al0 >= 0.0f) ? al0 : NEG_SLOPE * al0;
    al1 = (al1 >= 0.0f) ? al1 : NEG_SLOPE * al1;
    al2 = (al2 >= 0.0f) ? al2 : NEG_SLOPE * al2;
    al3 = (al3 >= 0.0f) ? al3 : NEG_SLOPE * al3;
    __half2 e01 = __floats2half2_rn(__expf(al0), __expf(al1));
    __half2 e23 = __floats2half2_rn(__expf(al2), __expf(al3));
    int4 rec;
    rec.x = src;
    rec.y = *reinterpret_cast<int*>(&e01);
    rec.z = *reinterpret_cast<int*>(&e23);
    rec.w = 0;
    int pos = atomicAdd(&g_cursor[dst], 1);
    g_rec[pos] = rec;
}

// ---------------- K5: gather-aggregate (independent warp per dst node) -------
__device__ __forceinline__ float rec_w(const int4& r, int h) {
    int raw = (h < 2) ? r.y : r.z;
    __half2 pair = *reinterpret_cast<__half2*>(&raw);
    float2 f = __half22float2(pair);
    return (h & 1) ? f.y : f.x;
}

__global__ void k_agg(const float* __restrict__ bias, float* __restrict__ out) {
    const int n = (blockIdx.x * blockDim.x + threadIdx.x) >> 5;
    if (n >= NN) return;
    const int lane = threadIdx.x & 31;
    const int start = g_ptr[n];
    const int deg = g_deg[n];
    const int h = lane >> 3;

    float4 acc = make_float4(0.f, 0.f, 0.f, 0.f);
    float dsum = 0.0f;
    int i = start;
    const int end = start + deg;
    for (; i + 4 <= end; i += 4) {
        const int4 r0 = __ldg(&g_rec[i]);
        const int4 r1 = __ldg(&g_rec[i + 1]);
        const int4 r2 = __ldg(&g_rec[i + 2]);
        const int4 r3 = __ldg(&g_rec[i + 3]);
        const float w0 = rec_w(r0, h), w1 = rec_w(r1, h);
        const float w2 = rec_w(r2, h), w3 = rec_w(r3, h);
        const unsigned long long hb0 = *reinterpret_cast<const unsigned long long*>(
            &g_h16[(size_t)r0.x * HCF + lane * 4]);
        const unsigned long long hb1 = *reinterpret_cast<const unsigned long long*>(
            &g_h16[(size_t)r1.x * HCF + lane * 4]);
        const unsigned long long hb2 = *reinterpret_cast<const unsigned long long*>(
            &g_h16[(size_t)r2.x * HCF + lane * 4]);
        const unsigned long long hb3 = *reinterpret_cast<const unsigned long long*>(
            &g_h16[(size_t)r3.x * HCF + lane * 4]);
        const __half2* p0 = reinterpret_cast<const __half2*>(&hb0);
        const __half2* p1 = reinterpret_cast<const __half2*>(&hb1);
        const __half2* p2 = reinterpret_cast<const __half2*>(&hb2);
        const __half2* p3 = reinterpret_cast<const __half2*>(&hb3);
        float2 a0 = __half22float2(p0[0]), b0 = __half22float2(p0[1]);
        float2 a1 = __half22float2(p1[0]), b1 = __half22float2(p1[1]);
        float2 a2 = __half22float2(p2[0]), b2 = __half22float2(p2[1]);
        float2 a3 = __half22float2(p3[0]), b3 = __half22float2(p3[1]);
        dsum += (w0 + w1) + (w2 + w3);
        acc.x += w0 * a0.x + w1 * a1.x + w2 * a2.x + w3 * a3.x;
        acc.y += w0 * a0.y + w1 * a1.y + w2 * a2.y + w3 * a3.y;
        acc.z += w0 * b0.x + w1 * b1.x + w2 * b2.x + w3 * b3.x;
        acc.w += w0 * b0.y + w1 * b1.y + w2 * b2.y + w3 * b3.y;
    }
    for (; i < end; i++) {
        const int4 r0 = __ldg(&g_rec[i]);
        const float w0 = rec_w(r0, h);
        const unsigned long long hb0 = *reinterpret_cast<const unsigned long long*>(
            &g_h16[(size_t)r0.x * HCF + lane * 4]);
        const __half2* p0 = reinterpret_cast<const __half2*>(&hb0);
        float2 a0 = __half22float2(p0[0]), b0 = __half22float2(p0[1]);
        dsum += w0;
        acc.x += w0 * a0.x; acc.y += w0 * a0.y;
        acc.z += w0 * b0.x; acc.w += w0 * b0.y;
    }
    const float inv = 1.0f / (dsum + 1e-16f);
    const float4 b4 = *reinterpret_cast<const float4*>(&bias[lane * 4]);
    acc.x = acc.x * inv + b4.x; acc.y = acc.y * inv + b4.y;
    acc.z = acc.z * inv + b4.z; acc.w = acc.w * inv + b4.w;
    *reinterpret_cast<float4*>(&out[(size_t)n * HCF + lane * 4]) = acc;
}

// ---------------- K6: group sum / sumsq / counts (sorted, flush-on-change) ---
__global__ void k_stats(const int* __restrict__ batch,
                        const float* __restrict__ out) {
    __shared__ int sb[64];
    const int b0 = blockIdx.x * 64;
    if (threadIdx.x < 64)
        sb[threadIdx.x] = (b0 + threadIdx.x < NN) ? batch[b0 + threadIdx.x] : -1;
    __syncthreads();
    const int j = threadIdx.x;   // 0..127
    float s = 0.f, ss = 0.f;
    int cnt = 0;
    int cur = sb[0];
    for (int i = 0; i < 64; i++) {
        int g = sb[i];
        if (g < 0) break;
        float v = out[(size_t)(b0 + i) * HCF + j];
        if (g != cur) {
            atomicAdd(&g_gsum[cur * HCF + j], s);
            atomicAdd(&g_gss[cur * HCF + j], ss);
            if (j == 0) atomicAdd(&g_gcnt[cur], cnt);
            s = 0.f; ss = 0.f; cnt = 0; cur = g;
        }
        s += v; ss += v * v; cnt++;
    }
    if (cur >= 0) {
        atomicAdd(&g_gsum[cur * HCF + j], s);
        atomicAdd(&g_gss[cur * HCF + j], ss);
        if (j == 0) atomicAdd(&g_gcnt[cur], cnt);
    }
}

// ---------------- K7: per (group, feature) affine params ---------------------
__global__ void k_params(const float* __restrict__ gnw,
                         const float* __restrict__ gnb,
                         const float* __restrict__ gms) {
    int idx = blockIdx.x * blockDim.x + threadIdx.x;
    if (idx >= GG * HCF) return;
    const int j = idx & (HCF - 1);
    int cnt = g_gcnt[idx >> 7];
    float fc = (float)(cnt > 0 ? cnt : 1);
    float m = g_gsum[idx] / fc;
    float sj = gms[j];
    float var = g_gss[idx] / fc - 2.0f * sj * m * m + sj * sj * m * m;
    float inv = rsqrtf(fmaxf(var, 0.0f) + 1e-5f);
    float A = gnw[j] * inv;
    g_A[idx] = A;
    g_B[idx] = gnb[j] - A * sj * m;
}

// ---------------- K8: normalize (out = out*A[g,j] + B[g,j]) ------------------
__global__ void k_norm(const int* __restrict__ batch, float* __restrict__ out) {
    int idx = blockIdx.x * blockDim.x + threadIdx.x;
    if (idx >= NN * (HCF / 4)) return;
    const int n = idx >> 5;
    const int off = (idx & 31) * 4;
    const int g = batch[n];
    float4 v = reinterpret_cast<float4*>(out)[idx];
    const float4 A = *reinterpret_cast<const float4*>(&g_A[g * HCF + off]);
    const float4 B = *reinterpret_cast<const float4*>(&g_B[g * HCF + off]);
    v.x = v.x * A.x + B.x; v.y = v.y * A.y + B.y;
    v.z = v.z * A.z + B.z; v.w = v.w * A.w + B.w;
    reinterpret_cast<float4*>(out)[idx] = v;
}

// ---------------- launch -----------------------------------------------------
extern "C" void kernel_launch(void* const* d_in, const int* in_sizes, int n_in,
                              void* d_out, int out_size) {
    const float *x = 0, *ea = 0, *W = 0;
    const int *ei = 0, *batch = 0;
    const float* small[8] = {0, 0, 0, 0, 0, 0, 0, 0};
    int nsmall = 0;
    for (int i = 0; i < n_in; i++) {
        int sz = in_sizes[i];
        if      (sz == NN * HCF)   x     = (const float*)d_in[i];
        else if (sz == 2 * EE)     ei    = (const int*)d_in[i];
        else if (sz == EE)         ea    = (const float*)d_in[i];
        else if (sz == HCF * HCF)  W     = (const float*)d_in[i];
        else if (sz == NN)         batch = (const int*)d_in[i];
        else if (sz == HCF && nsmall < 8) small[nsmall++] = (const float*)d_in[i];
    }
    const float* att_src  = small[0];
    const float* att_dst  = small[1];
    const float* W_edge   = small[2];
    const float* att_edge = small[3];
    const float* bias     = small[4];
    const float* gnw      = small[5];
    const float* gnb      = small[6];
    const float* gms      = small[7];
    float* out = (float*)d_out;

    // Lazy-created side stream + events (host objects, no device memory; made
    // on the correctness call, i.e. outside graph capture).
    static cudaStream_t s2 = 0;
    static cudaEvent_t evA = 0, evB = 0;
    if (!s2) {
        cudaStreamCreateWithFlags(&s2, cudaStreamNonBlocking);
        cudaEventCreateWithFlags(&evA, cudaEventDisableTiming);
        cudaEventCreateWithFlags(&evB, cudaEventDisableTiming);
    }

    k_init  <<<(NN + 255) / 256, 256>>>(W_edge, att_edge);
    cudaEventRecord(evA, 0);
    cudaStreamWaitEvent(s2, evA, 0);
    // Submission order keeps k_gemm as the 4th launch (ncu's capture index)
    // while execution order/dependencies are unchanged.
    k_deg   <<<(EE + 255) / 256, 256, 0, s2>>>(ei);
    k_scan_a<<<NB_SCAN, 1024, 0, s2>>>();
    k_gemm  <<<NN / MT, 128>>>(x, W, att_src, att_dst);
    k_scan_b<<<1, 128, 0, s2>>>();
    k_scan_c<<<(NN + 255) / 256, 256, 0, s2>>>();
    cudaEventRecord(evB, s2);

    // Join: k_edge needs both the GEMM outputs and the scan results.
    cudaStreamWaitEvent(0, evB, 0);
    k_edge  <<<(EE + 255) / 256, 256>>>(ei, ea);
    k_agg   <<<NN / 8, 256>>>(bias, out);
    k_stats <<<(NN + 63) / 64, 128>>>(batch, out);
    k_params<<<(GG * HCF + 255) / 256, 256>>>(gnw, gnb, gms);
    k_norm  <<<(NN * (HCF / 4) + 255) / 256, 256>>>(batch, out);
}

// round 17
// speedup vs baseline: 1.4664x; 1.4376x over previous
#include <cuda_runtime.h>
#include <cuda_fp16.h>

// Problem constants (fixed by the dataset)
#define NN 100000
#define EE 1600000
#define HCF 128      // H*C
#define HH 4
#define GG 16
#define NEG_SLOPE 0.2f
#define NB_SCAN ((NN + 1023) / 1024)   // 98 scan blocks
#define GEMM_MT 64                      // nodes per gemm block

// ---------------- static device scratch (no allocations allowed) -------------
__device__ __align__(16) __half g_h16[(size_t)NN * HCF];       // 25.6 MB (fp16 h)
__device__ __align__(16) __half g_w16[HCF * HCF];              // fp16 W
__device__ __align__(16) float  g_asrc[NN * HH];
__device__ __align__(16) float  g_adst[NN * HH];
__device__ int   g_deg[NN];
__device__ int   g_ptr[NN];
__device__ int   g_cursor[NN];
__device__ int   g_bsum[128];
__device__ __align__(16) int4 g_rec[EE];                       // 25.6 MB packed CSR
__device__ float g_gsum[GG * HCF];
__device__ float g_gss[GG * HCF];
__device__ int   g_gcnt[GG];
__device__ float g_ce[HH];
__device__ __align__(16) float g_A[GG * HCF];
__device__ __align__(16) float g_B[GG * HCF];

// ---------------- K0: init + per-head edge constant + W->fp16 ---------------
__global__ void k_init(const float* __restrict__ W,
                       const float* __restrict__ W_edge,
                       const float* __restrict__ att_edge) {
    int idx = blockIdx.x * blockDim.x + threadIdx.x;
    if (idx < NN)      g_deg[idx] = 0;
    if (idx < GG * HCF) { g_gsum[idx] = 0.0f; g_gss[idx] = 0.0f; }
    if (idx < GG)      g_gcnt[idx] = 0;
    if (idx < HCF * HCF) g_w16[idx] = __float2half_rn(W[idx]);
    if (blockIdx.x == 0 && threadIdx.x < HCF) {
        int j = threadIdx.x;
        float v = W_edge[j] * att_edge[j];
        #pragma unroll
        for (int o = 16; o > 0; o >>= 1)
            v += __shfl_down_sync(0xffffffffu, v, o);
        if ((j & 31) == 0) g_ce[j >> 5] = v;
    }
}

// ---------------- K1: h = x @ W via HMMA (m16n8k16 f16->f32) -----------------
// 256 threads = 8 warps. Warp w: m-tile = (w&3)*16 nodes, col-half = (w>>2)*64.
// x converted fp32->fp16 into smem (stride 136 halves: conflict-free ldmatrix);
// W staged from g_w16 in two 64-row phases. Epilogue stores fp16 h and the
// per-head a_src/a_dst dots directly from C fragments.
__global__ __launch_bounds__(256) void k_gemm(
        const float* __restrict__ x,
        const float* __restrict__ att_src, const float* __restrict__ att_dst) {
    __shared__ __align__(16) __half xa[64 * 136];   // [node][k]
    __shared__ __align__(16) __half ws[64 * 136];   // [k-phase-row][col]
    const int tid = threadIdx.x;
    const int lane = tid & 31;
    const int warp = tid >> 5;
    const int m0 = (warp & 3) * 16;
    const int c0 = (warp >> 2) * 64;
    const int n0 = blockIdx.x * GEMM_MT;

    // ---- load x tile (fp32 -> fp16), clamped in-bounds for the tail block ----
    for (int i = tid; i < 2048; i += 256) {          // 2048 float4s = 64x128
        int m = i >> 5;
        int kq = (i & 31) * 4;
        int nn = n0 + m; if (nn >= NN) nn = NN - 1;
        float4 v = *reinterpret_cast<const float4*>(&x[(size_t)nn * HCF + kq]);
        __half2 h0 = __floats2half2_rn(v.x, v.y);
        __half2 h1 = __floats2half2_rn(v.z, v.w);
        *reinterpret_cast<uint2*>(&xa[m * 136 + kq]) =
            make_uint2(*reinterpret_cast<unsigned*>(&h0),
                       *reinterpret_cast<unsigned*>(&h1));
    }
    // ---- load W rows 0..63 ----
    for (int i = tid; i < 1024; i += 256) {          // 1024 uint4s = 64x128 halves
        int kr = i >> 4;
        int c8 = (i & 15) * 8;
        *reinterpret_cast<uint4*>(&ws[kr * 136 + c8]) =
            *reinterpret_cast<const uint4*>(&g_w16[kr * HCF + c8]);
    }
    __syncthreads();

    float c[8][4];
    #pragma unroll
    for (int t = 0; t < 8; t++) { c[t][0] = c[t][1] = c[t][2] = c[t][3] = 0.f; }

    const unsigned abase = (unsigned)__cvta_generic_to_shared(
        &xa[(m0 + (lane & 7) + ((lane >> 3) & 1) * 8) * 136 + ((lane >> 4) * 8)]);
    const int brow = (lane & 7) + ((lane >> 3) & 1) * 8;
    const int bcol = c0 + (lane >> 4) * 8;

    #pragma unroll
    for (int it = 0; it < 8; it++) {
        if (it == 4) {                               // swap in W rows 64..127
            __syncthreads();
            for (int i = tid; i < 1024; i += 256) {
                int kr = i >> 4;
                int c8 = (i & 15) * 8;
                *reinterpret_cast<uint4*>(&ws[kr * 136 + c8]) =
                    *reinterpret_cast<const uint4*>(&g_w16[(64 + kr) * HCF + c8]);
            }
            __syncthreads();
        }
        unsigned a0, a1, a2, a3;
        asm volatile(
            "ldmatrix.sync.aligned.m8n8.x4.shared.b16 {%0,%1,%2,%3}, [%4];"
            : "=r"(a0), "=r"(a1), "=r"(a2), "=r"(a3)
            : "r"(abase + it * 32));
        const int krow = (it & 3) * 16 + brow;
        unsigned b[8][2];
        #pragma unroll
        for (int p = 0; p < 4; p++) {
            unsigned baddr = (unsigned)__cvta_generic_to_shared(
                &ws[krow * 136 + bcol + p * 16]);
            unsigned r0, r1, r2, r3;
            asm volatile(
                "ldmatrix.sync.aligned.m8n8.x4.trans.shared.b16 {%0,%1,%2,%3}, [%4];"
                : "=r"(r0), "=r"(r1), "=r"(r2), "=r"(r3) : "r"(baddr));
            b[2 * p][0] = r0; b[2 * p][1] = r1;
            b[2 * p + 1][0] = r2; b[2 * p + 1][1] = r3;
        }
        #pragma unroll
        for (int t = 0; t < 8; t++) {
            asm volatile(
                "mma.sync.aligned.m16n8k16.row.col.f32.f16.f16.f32 "
                "{%0,%1,%2,%3}, {%4,%5,%6,%7}, {%8,%9}, {%0,%1,%2,%3};"
                : "+f"(c[t][0]), "+f"(c[t][1]), "+f"(c[t][2]), "+f"(c[t][3])
                : "r"(a0), "r"(a1), "r"(a2), "r"(a3), "r"(b[t][0]), "r"(b[t][1]));
        }
    }

    // ---- epilogue: h fp16 store + per-head att dots from fragments ----
    const int group = lane >> 2, qid = lane & 3;
    const int na = n0 + m0 + group;
    const int nb = na + 8;
    float sA[2] = {0.f, 0.f}, sB[2] = {0.f, 0.f};
    float dA[2] = {0.f, 0.f}, dB[2] = {0.f, 0.f};
    #pragma unroll
    for (int t = 0; t < 8; t++) {
        const int col = c0 + t * 8 + qid * 2;
        const float as0 = att_src[col], as1 = att_src[col + 1];
        const float ad0 = att_dst[col], ad1 = att_dst[col + 1];
        const int hh = t >> 2;
        sA[hh] += c[t][0] * as0 + c[t][1] * as1;
        dA[hh] += c[t][0] * ad0 + c[t][1] * ad1;
        sB[hh] += c[t][2] * as0 + c[t][3] * as1;
        dB[hh] += c[t][2] * ad0 + c[t][3] * ad1;
        __half2 ha = __floats2half2_rn(c[t][0], c[t][1]);
        __half2 hb = __floats2half2_rn(c[t][2], c[t][3]);
        if (na < NN) *reinterpret_cast<__half2*>(&g_h16[(size_t)na * HCF + col]) = ha;
        if (nb < NN) *reinterpret_cast<__half2*>(&g_h16[(size_t)nb * HCF + col]) = hb;
    }
    #pragma unroll
    for (int o = 1; o <= 2; o <<= 1) {
        #pragma unroll
        for (int hh = 0; hh < 2; hh++) {
            sA[hh] += __shfl_xor_sync(0xffffffffu, sA[hh], o);
            sB[hh] += __shfl_xor_sync(0xffffffffu, sB[hh], o);
            dA[hh] += __shfl_xor_sync(0xffffffffu, dA[hh], o);
            dB[hh] += __shfl_xor_sync(0xffffffffu, dB[hh], o);
        }
    }
    if (qid == 0) {
        const int hb0 = c0 >> 5;     // first head of this warp's 64 cols
        if (na < NN) {
            g_asrc[na * HH + hb0] = sA[0]; g_asrc[na * HH + hb0 + 1] = sA[1];
            g_adst[na * HH + hb0] = dA[0]; g_adst[na * HH + hb0 + 1] = dA[1];
        }
        if (nb < NN) {
            g_asrc[nb * HH + hb0] = sB[0]; g_asrc[nb * HH + hb0 + 1] = sB[1];
            g_adst[nb * HH + hb0] = dB[0]; g_adst[nb * HH + hb0 + 1] = dB[1];
        }
    }
}

// ---------------- K2: dst-degree histogram -----------------------------------
__global__ void k_deg(const int* __restrict__ ei) {
    int e = blockIdx.x * blockDim.x + threadIdx.x;
    if (e < EE) atomicAdd(&g_deg[__ldg(&ei[EE + e])], 1);
}

// ---------------- K3a: block-wise inclusive scan of degrees ------------------
__global__ void k_scan_a() {
    __shared__ int sh[1024];
    const int t = threadIdx.x;
    const int i = blockIdx.x * 1024 + t;
    const int v = (i < NN) ? g_deg[i] : 0;
    sh[t] = v;
    __syncthreads();
    #pragma unroll
    for (int o = 1; o < 1024; o <<= 1) {
        int u = (t >= o) ? sh[t - o] : 0;
        __syncthreads();
        sh[t] += u;
        __syncthreads();
    }
    if (i < NN) g_ptr[i] = sh[t] - v;
    if (t == 1023) g_bsum[blockIdx.x] = sh[1023];
}

// ---------------- K3b: scan the block totals ---------------------------------
__global__ void k_scan_b() {
    __shared__ int sh[128];
    const int t = threadIdx.x;
    const int v = (t < NB_SCAN) ? g_bsum[t] : 0;
    sh[t] = v;
    __syncthreads();
    #pragma unroll
    for (int o = 1; o < 128; o <<= 1) {
        int u = (t >= o) ? sh[t - o] : 0;
        __syncthreads();
        sh[t] += u;
        __syncthreads();
    }
    if (t < NB_SCAN) g_bsum[t] = sh[t] - v;
}

// ---------------- K3c: add block offsets, init cursor ------------------------
__global__ void k_scan_c() {
    int i = blockIdx.x * blockDim.x + threadIdx.x;
    if (i < NN) {
        int p = g_ptr[i] + g_bsum[i >> 10];
        g_ptr[i] = p;
        g_cursor[i] = p;
    }
}

// ---------------- K4: alpha -> leaky -> exp -> packed CSR record -------------
__global__ void k_edge(const int* __restrict__ ei, const float* __restrict__ ea) {
    int e = blockIdx.x * blockDim.x + threadIdx.x;
    if (e >= EE) return;
    const int src = ei[e];
    const int dst = ei[EE + e];
    const float4 as = *reinterpret_cast<const float4*>(&g_asrc[src * HH]);
    const float4 ad = *reinterpret_cast<const float4*>(&g_adst[dst * HH]);
    const float w = ea[e];
    float al0 = as.x + ad.x + w * g_ce[0];
    float al1 = as.y + ad.y + w * g_ce[1];
    float al2 = as.z + ad.z + w * g_ce[2];
    float al3 = as.w + ad.w + w * g_ce[3];
    al0 = (al0 >= 0.0f) ? al0 : NEG_SLOPE * al0;
    al1 = (al1 >= 0.0f) ? al1 : NEG_SLOPE * al1;
    al2 = (al2 >= 0.0f) ? al2 : NEG_SLOPE * al2;
    al3 = (al3 >= 0.0f) ? al3 : NEG_SLOPE * al3;
    __half2 e01 = __floats2half2_rn(__expf(al0), __expf(al1));
    __half2 e23 = __floats2half2_rn(__expf(al2), __expf(al3));
    int4 rec;
    rec.x = src;
    rec.y = *reinterpret_cast<int*>(&e01);
    rec.z = *reinterpret_cast<int*>(&e23);
    rec.w = 0;
    int pos = atomicAdd(&g_cursor[dst], 1);
    g_rec[pos] = rec;
}

// ---------------- K5: gather-aggregate (independent warp per dst node) -------
__device__ __forceinline__ float rec_w(const int4& r, int h) {
    int raw = (h < 2) ? r.y : r.z;
    __half2 pair = *reinterpret_cast<__half2*>(&raw);
    float2 f = __half22float2(pair);
    return (h & 1) ? f.y : f.x;
}

__global__ void k_agg(const float* __restrict__ bias, float* __restrict__ out) {
    const int n = (blockIdx.x * blockDim.x + threadIdx.x) >> 5;
    if (n >= NN) return;
    const int lane = threadIdx.x & 31;
    const int start = g_ptr[n];
    const int deg = g_deg[n];
    const int h = lane >> 3;

    float4 acc = make_float4(0.f, 0.f, 0.f, 0.f);
    float dsum = 0.0f;
    int i = start;
    const int end = start + deg;
    for (; i + 4 <= end; i += 4) {
        const int4 r0 = __ldg(&g_rec[i]);
        const int4 r1 = __ldg(&g_rec[i + 1]);
        const int4 r2 = __ldg(&g_rec[i + 2]);
        const int4 r3 = __ldg(&g_rec[i + 3]);
        const float w0 = rec_w(r0, h), w1 = rec_w(r1, h);
        const float w2 = rec_w(r2, h), w3 = rec_w(r3, h);
        const unsigned long long hb0 = *reinterpret_cast<const unsigned long long*>(
            &g_h16[(size_t)r0.x * HCF + lane * 4]);
        const unsigned long long hb1 = *reinterpret_cast<const unsigned long long*>(
            &g_h16[(size_t)r1.x * HCF + lane * 4]);
        const unsigned long long hb2 = *reinterpret_cast<const unsigned long long*>(
            &g_h16[(size_t)r2.x * HCF + lane * 4]);
        const unsigned long long hb3 = *reinterpret_cast<const unsigned long long*>(
            &g_h16[(size_t)r3.x * HCF + lane * 4]);
        const __half2* p0 = reinterpret_cast<const __half2*>(&hb0);
        const __half2* p1 = reinterpret_cast<const __half2*>(&hb1);
        const __half2* p2 = reinterpret_cast<const __half2*>(&hb2);
        const __half2* p3 = reinterpret_cast<const __half2*>(&hb3);
        float2 a0 = __half22float2(p0[0]), b0 = __half22float2(p0[1]);
        float2 a1 = __half22float2(p1[0]), b1 = __half22float2(p1[1]);
        float2 a2 = __half22float2(p2[0]), b2 = __half22float2(p2[1]);
        float2 a3 = __half22float2(p3[0]), b3 = __half22float2(p3[1]);
        dsum += (w0 + w1) + (w2 + w3);
        acc.x += w0 * a0.x + w1 * a1.x + w2 * a2.x + w3 * a3.x;
        acc.y += w0 * a0.y + w1 * a1.y + w2 * a2.y + w3 * a3.y;
        acc.z += w0 * b0.x + w1 * b1.x + w2 * b2.x + w3 * b3.x;
        acc.w += w0 * b0.y + w1 * b1.y + w2 * b2.y + w3 * b3.y;
    }
    for (; i < end; i++) {
        const int4 r0 = __ldg(&g_rec[i]);
        const float w0 = rec_w(r0, h);
        const unsigned long long hb0 = *reinterpret_cast<const unsigned long long*>(
            &g_h16[(size_t)r0.x * HCF + lane * 4]);
        const __half2* p0 = reinterpret_cast<const __half2*>(&hb0);
        float2 a0 = __half22float2(p0[0]), b0 = __half22float2(p0[1]);
        dsum += w0;
        acc.x += w0 * a0.x; acc.y += w0 * a0.y;
        acc.z += w0 * b0.x; acc.w += w0 * b0.y;
    }
    const float inv = 1.0f / (dsum + 1e-16f);
    const float4 b4 = *reinterpret_cast<const float4*>(&bias[lane * 4]);
    acc.x = acc.x * inv + b4.x; acc.y = acc.y * inv + b4.y;
    acc.z = acc.z * inv + b4.z; acc.w = acc.w * inv + b4.w;
    *reinterpret_cast<float4*>(&out[(size_t)n * HCF + lane * 4]) = acc;
}

// ---------------- K6: group sum / sumsq / counts (sorted, flush-on-change) ---
__global__ void k_stats(const int* __restrict__ batch,
                        const float* __restrict__ out) {
    __shared__ int sb[64];
    const int b0 = blockIdx.x * 64;
    if (threadIdx.x < 64)
        sb[threadIdx.x] = (b0 + threadIdx.x < NN) ? batch[b0 + threadIdx.x] : -1;
    __syncthreads();
    const int j = threadIdx.x;   // 0..127
    float s = 0.f, ss = 0.f;
    int cnt = 0;
    int cur = sb[0];
    for (int i = 0; i < 64; i++) {
        int g = sb[i];
        if (g < 0) break;
        float v = out[(size_t)(b0 + i) * HCF + j];
        if (g != cur) {
            atomicAdd(&g_gsum[cur * HCF + j], s);
            atomicAdd(&g_gss[cur * HCF + j], ss);
            if (j == 0) atomicAdd(&g_gcnt[cur], cnt);
            s = 0.f; ss = 0.f; cnt = 0; cur = g;
        }
        s += v; ss += v * v; cnt++;
    }
    if (cur >= 0) {
        atomicAdd(&g_gsum[cur * HCF + j], s);
        atomicAdd(&g_gss[cur * HCF + j], ss);
        if (j == 0) atomicAdd(&g_gcnt[cur], cnt);
    }
}

// ---------------- K7: per (group, feature) affine params ---------------------
__global__ void k_params(const float* __restrict__ gnw,
                         const float* __restrict__ gnb,
                         const float* __restrict__ gms) {
    int idx = blockIdx.x * blockDim.x + threadIdx.x;
    if (idx >= GG * HCF) return;
    const int j = idx & (HCF - 1);
    int cnt = g_gcnt[idx >> 7];
    float fc = (float)(cnt > 0 ? cnt : 1);
    float m = g_gsum[idx] / fc;
    float sj = gms[j];
    float var = g_gss[idx] / fc - 2.0f * sj * m * m + sj * sj * m * m;
    float inv = rsqrtf(fmaxf(var, 0.0f) + 1e-5f);
    float A = gnw[j] * inv;
    g_A[idx] = A;
    g_B[idx] = gnb[j] - A * sj * m;
}

// ---------------- K8: normalize (out = out*A[g,j] + B[g,j]) ------------------
__global__ void k_norm(const int* __restrict__ batch, float* __restrict__ out) {
    int idx = blockIdx.x * blockDim.x + threadIdx.x;
    if (idx >= NN * (HCF / 4)) return;
    const int n = idx >> 5;
    const int off = (idx & 31) * 4;
    const int g = batch[n];
    float4 v = reinterpret_cast<float4*>(out)[idx];
    const float4 A = *reinterpret_cast<const float4*>(&g_A[g * HCF + off]);
    const float4 B = *reinterpret_cast<const float4*>(&g_B[g * HCF + off]);
    v.x = v.x * A.x + B.x; v.y = v.y * A.y + B.y;
    v.z = v.z * A.z + B.z; v.w = v.w * A.w + B.w;
    reinterpret_cast<float4*>(out)[idx] = v;
}

// ---------------- launch -----------------------------------------------------
extern "C" void kernel_launch(void* const* d_in, const int* in_sizes, int n_in,
                              void* d_out, int out_size) {
    const float *x = 0, *ea = 0, *W = 0;
    const int *ei = 0, *batch = 0;
    const float* small[8] = {0, 0, 0, 0, 0, 0, 0, 0};
    int nsmall = 0;
    for (int i = 0; i < n_in; i++) {
        int sz = in_sizes[i];
        if      (sz == NN * HCF)   x     = (const float*)d_in[i];
        else if (sz == 2 * EE)     ei    = (const int*)d_in[i];
        else if (sz == EE)         ea    = (const float*)d_in[i];
        else if (sz == HCF * HCF)  W     = (const float*)d_in[i];
        else if (sz == NN)         batch = (const int*)d_in[i];
        else if (sz == HCF && nsmall < 8) small[nsmall++] = (const float*)d_in[i];
    }
    const float* att_src  = small[0];
    const float* att_dst  = small[1];
    const float* W_edge   = small[2];
    const float* att_edge = small[3];
    const float* bias     = small[4];
    const float* gnw      = small[5];
    const float* gnb      = small[6];
    const float* gms      = small[7];
    float* out = (float*)d_out;

    // Lazy-created side stream + events (host objects, no device memory; made
    // on the correctness call, i.e. outside graph capture).
    static cudaStream_t s2 = 0;
    static cudaEvent_t evA = 0, evB = 0;
    if (!s2) {
        cudaStreamCreateWithFlags(&s2, cudaStreamNonBlocking);
        cudaEventCreateWithFlags(&evA, cudaEventDisableTiming);
        cudaEventCreateWithFlags(&evB, cudaEventDisableTiming);
    }

    k_init  <<<(NN + 255) / 256, 256>>>(W, W_edge, att_edge);
    cudaEventRecord(evA, 0);
    cudaStreamWaitEvent(s2, evA, 0);
    // Submission order keeps k_gemm as the 4th launch (ncu's capture index)
    // while execution order/dependencies are unchanged.
    k_deg   <<<(EE + 255) / 256, 256, 0, s2>>>(ei);
    k_scan_a<<<NB_SCAN, 1024, 0, s2>>>();
    k_gemm  <<<(NN + GEMM_MT - 1) / GEMM_MT, 256>>>(x, att_src, att_dst);
    k_scan_b<<<1, 128, 0, s2>>>();
    k_scan_c<<<(NN + 255) / 256, 256, 0, s2>>>();
    cudaEventRecord(evB, s2);

    // Join: k_edge needs both the GEMM outputs and the scan results.
    cudaStreamWaitEvent(0, evB, 0);
    k_edge  <<<(EE + 255) / 256, 256>>>(ei, ea);
    k_agg   <<<NN / 8, 256>>>(bias, out);
    k_stats <<<(NN + 63) / 64, 128>>>(batch, out);
    k_params<<<(GG * HCF + 255) / 256, 256>>>(gnw, gnb, gms);
    k_norm  <<<(NN * (HCF / 4) + 255) / 256, 256>>>(batch, out);
}